// round 1
// baseline (speedup 1.0000x reference)
#include <cuda_runtime.h>

// Complete K=8-ary tree, depth 5.
#define NN        37449   // total nodes
#define L5_START  4681    // leaf level start
#define L5_COUNT  32768
#define L4_START  585
#define L4_COUNT  4096
#define L3_START  73
#define L2_START  9
#define L1_START  1

// Precomputed sigmoid(weights), shared by all rows (L2-resident, 150 KB).
__device__ float g_sw[NN];

__global__ void sigmoid_kernel(const float* __restrict__ w) {
    int i = blockIdx.x * blockDim.x + threadIdx.x;
    if (i < NN) {
        g_sw[i] = 1.0f / (1.0f + __expf(-w[i]));
    }
}

__device__ __forceinline__ float clamp01(float v) {
    return fminf(fmaxf(v, 0.0f), 1.0f);
}

// One block per batch row. 512 threads.
__global__ __launch_bounds__(512, 4)
void tree_kernel(const float* __restrict__ in, float* __restrict__ out) {
    __shared__ __align__(16) float s_l4[L4_COUNT];  // 16 KB
    __shared__ __align__(16) float s_l3[512];       //  2 KB
    __shared__ __align__(16) float s_l2[64];
    __shared__ __align__(16) float s_l1[8];

    const int tid = threadIdx.x;
    const float* __restrict__ rin  = in  + (size_t)blockIdx.x * NN;
    float*       __restrict__ rout = out + (size_t)blockIdx.x * NN;

    // ---- Stream leaves: copy to output + compute level-4 parents ----
    // Leaf local index l: children of level-4 parent g are leaves [8g, 8g+8).
    // Lanes (8m..8m+7) of each warp hold one parent's children (512 | 8).
    #pragma unroll 4
    for (int it = 0; it < L5_COUNT / 512; ++it) {
        int l = it * 512 + tid;
        float x  = __ldg(rin + L5_START + l);     // coalesced DRAM read (once)
        float sv = __ldg(g_sw + L5_START + l);    // coalesced, L2-resident
        rout[L5_START + l] = x;                   // identity copy of leaf
        float v = x * sv;
        v += __shfl_xor_sync(0xffffffffu, v, 1);
        v += __shfl_xor_sync(0xffffffffu, v, 2);
        v += __shfl_xor_sync(0xffffffffu, v, 4);
        if ((tid & 7) == 0) s_l4[l >> 3] = clamp01(v);
    }
    __syncthreads();

    // ---- Level 3: 512 parents, children are s_l4[8j .. 8j+8) ----
    {
        const float4* p = reinterpret_cast<const float4*>(s_l4) + 2 * tid;
        float4 a = p[0], b = p[1];                 // conflict-free (32 banks)
        const float* swp = g_sw + L4_START + 8 * tid;
        float v = a.x * __ldg(swp + 0) + a.y * __ldg(swp + 1)
                + a.z * __ldg(swp + 2) + a.w * __ldg(swp + 3)
                + b.x * __ldg(swp + 4) + b.y * __ldg(swp + 5)
                + b.z * __ldg(swp + 6) + b.w * __ldg(swp + 7);
        s_l3[tid] = clamp01(v);
    }
    __syncthreads();

    // ---- Level 2: 64 parents ----
    if (tid < 64) {
        const float4* p = reinterpret_cast<const float4*>(s_l3) + 2 * tid;
        float4 a = p[0], b = p[1];
        const float* swp = g_sw + L3_START + 8 * tid;
        float v = a.x * __ldg(swp + 0) + a.y * __ldg(swp + 1)
                + a.z * __ldg(swp + 2) + a.w * __ldg(swp + 3)
                + b.x * __ldg(swp + 4) + b.y * __ldg(swp + 5)
                + b.z * __ldg(swp + 6) + b.w * __ldg(swp + 7);
        s_l2[tid] = clamp01(v);
    }
    __syncthreads();

    // ---- Level 1: 8 parents ----
    if (tid < 8) {
        const float4* p = reinterpret_cast<const float4*>(s_l2) + 2 * tid;
        float4 a = p[0], b = p[1];
        const float* swp = g_sw + L2_START + 8 * tid;
        float v = a.x * __ldg(swp + 0) + a.y * __ldg(swp + 1)
                + a.z * __ldg(swp + 2) + a.w * __ldg(swp + 3)
                + b.x * __ldg(swp + 4) + b.y * __ldg(swp + 5)
                + b.z * __ldg(swp + 6) + b.w * __ldg(swp + 7);
        s_l1[tid] = clamp01(v);
    }
    __syncthreads();

    // ---- Level 0: root (thread 0) ----
    if (tid == 0) {
        const float4* p = reinterpret_cast<const float4*>(s_l1);
        float4 a = p[0], b = p[1];
        const float* swp = g_sw + L1_START;
        float v = a.x * __ldg(swp + 0) + a.y * __ldg(swp + 1)
                + a.z * __ldg(swp + 2) + a.w * __ldg(swp + 3)
                + b.x * __ldg(swp + 4) + b.y * __ldg(swp + 5)
                + b.z * __ldg(swp + 6) + b.w * __ldg(swp + 7);
        rout[0] = clamp01(v);
    }

    // ---- Write internal levels (coalesced from shared) ----
    #pragma unroll
    for (int it = 0; it < L4_COUNT / 512; ++it)
        rout[L4_START + it * 512 + tid] = s_l4[it * 512 + tid];
    rout[L3_START + tid] = s_l3[tid];
    if (tid < 64) rout[L2_START + tid] = s_l2[tid];
    if (tid < 8)  rout[L1_START + tid] = s_l1[tid];
}

extern "C" void kernel_launch(void* const* d_in, const int* in_sizes, int n_in,
                              void* d_out, int out_size) {
    const float* probs = (const float*)d_in[0];   // [2048, 37449] fp32
    const float* w     = (const float*)d_in[1];   // [37449] fp32
    float* out         = (float*)d_out;           // [2048, 37449] fp32

    const int batch = in_sizes[0] / NN;           // 2048

    sigmoid_kernel<<<(NN + 255) / 256, 256>>>(w);
    tree_kernel<<<batch, 512>>>(probs, out);
}

// round 3
// speedup vs baseline: 1.0161x; 1.0161x over previous
#include <cuda_runtime.h>

#define NN        37449   // total nodes
#define L5_START  4681    // leaf level start
#define L5_COUNT  32768
#define L4_START  585
#define L4_COUNT  4096
#define L3_START  73
#define L2_START  9
#define L1_START  1

// sigmoid(w) for all nodes (internal-level dots + head/tail scalars)
__device__ float g_sw[NN];
// 4 shifted copies of the leaf section: copy s stores leaf l at index
// ((4-s)&3)+l. For LB=s, vector k's 4 leaves start at copy index
// ((4-s)&3)+s+4k  (= 4+4k for s>0, 4k for s=0) -> 16B aligned.
__device__ __align__(16) float g_swl[4][L5_COUNT + 4];

__global__ void setup_kernel(const float* __restrict__ w) {
    int i = blockIdx.x * blockDim.x + threadIdx.x;
    if (i >= NN) return;
    float sv = 1.0f / (1.0f + __expf(-w[i]));
    g_sw[i] = sv;
    int l = i - L5_START;
    if (l >= 0) {
        #pragma unroll
        for (int s = 0; s < 4; ++s)
            g_swl[s][((4 - s) & 3) + l] = sv;
    }
}

// Streaming phase, templated on the row's leaf-base alignment LB.
// Vector k covers leaves [LB+4k, LB+4k+4). For each vector:
//   s = full 4-dot of products, a = low-parent part, b = high-parent part.
// Parent slot m (per warp) = b[lane 2m-1] + s[lane 2m] + a[lane 2m+1].
template<int LB>
__device__ __forceinline__ void stream_phase(
    const float* __restrict__ rin, float* __restrict__ rout,
    float* __restrict__ s_l4, float* __restrict__ s_edge, int tid)
{
    const float4* __restrict__ in4  = reinterpret_cast<const float4*>(rin  + L5_START + LB);
    float4*       __restrict__ out4 = reinterpret_cast<float4*>(rout + L5_START + LB);
    // 16B-aligned base: copy index ((4-LB)&3)+LB  (0 for LB==0, 4 otherwise)
    const float4* __restrict__ sw4  =
        reinterpret_cast<const float4*>(&g_swl[LB][((4 - LB) & 3) + LB]);
    const int lane = tid & 31;
    const int warp = tid >> 5;

    #pragma unroll 4
    for (int it = 0; it < 16; ++it) {
        const int k = it * 512 + tid;
        float4 x, sv;
        if (LB == 0 || k != 8191) {
            x  = __ldcs(in4 + k);
            sv = __ldg(sw4 + k);
            __stcs(out4 + k, x);
        } else {
            // Clipped tail vector: only leaves LB+32764 .. 32767 exist.
            float xt[4] = {0.f, 0.f, 0.f, 0.f};
            float st[4] = {0.f, 0.f, 0.f, 0.f};
            const float* rp = rin  + L5_START + LB + 32764;
            float*       wp = rout + L5_START + LB + 32764;
            const float* sp = &g_swl[LB][((4 - LB) & 3) + LB + 32764];
            #pragma unroll
            for (int j = 0; j < 4 - LB; ++j) {
                xt[j] = rp[j]; st[j] = sp[j]; wp[j] = xt[j];
            }
            x  = make_float4(xt[0], xt[1], xt[2], xt[3]);
            sv = make_float4(st[0], st[1], st[2], st[3]);
        }

        float q0 = x.x * sv.x, q1 = x.y * sv.y, q2 = x.z * sv.z, q3 = x.w * sv.w;
        float s = (q0 + q1) + (q2 + q3);
        float a, b;
        if (LB == 0) {
            a = s; b = 0.f;
        } else {
            // odd-k vectors straddle a parent boundary at local position 8.
            float ao, bo;
            if (LB == 1) { ao = (q0 + q1) + q2; bo = q3; }
            if (LB == 2) { ao = q0 + q1;        bo = q2 + q3; }
            if (LB == 3) { ao = q0;             bo = (q1 + q2) + q3; }
            bool odd = (k & 1);
            a = odd ? ao : s;
            b = odd ? bo : 0.f;
        }

        // Lane m (<16) assembles parent it*256 + warp*16 + m.
        float ss = __shfl_sync(0xffffffffu, s, (2 * lane)      & 31);
        float aa = __shfl_sync(0xffffffffu, a, (2 * lane + 1)  & 31);
        float bb = __shfl_sync(0xffffffffu, b, (2 * lane + 31) & 31);
        if (lane < 16) {
            float val = ss + aa;
            if (lane > 0) val += bb;        // lane-0 parents get their b in fixup
            s_l4[it * 256 + warp * 16 + lane] = val;
        }
        if (LB != 0 && lane == 31)
            s_edge[it * 16 + warp + 1] = b; // edge into parent (it*256+warp*16+16)
    }

    if (LB != 0 && tid == 0) {
        // Head leaves 0..LB-1 belong to parent 0.
        float h = 0.f;
        #pragma unroll
        for (int j = 0; j < LB; ++j) {
            float xv = rin[L5_START + j];
            rout[L5_START + j] = xv;
            h += xv * g_sw[L5_START + j];
        }
        s_edge[0] = h;
    }
}

__global__ __launch_bounds__(512)
void tree_kernel(const float* __restrict__ in, float* __restrict__ out)
{
    __shared__ __align__(16) float s_l4[L4_COUNT];   // raw (pre-clamp) parent sums
    __shared__ float s_edge[260];
    __shared__ __align__(16) float s_l3[512];
    __shared__ __align__(16) float s_l2[64];
    __shared__ __align__(16) float s_l1[8];

    const int tid = threadIdx.x;
    const int r   = blockIdx.x;
    const float* __restrict__ rin  = in  + (size_t)r * NN;
    float*       __restrict__ rout = out + (size_t)r * NN;
    const int lb = (4 - ((r + 1) & 3)) & 3;   // leaf-base alignment for this row

    switch (lb) {
        case 0: stream_phase<0>(rin, rout, s_l4, s_edge, tid); break;
        case 1: stream_phase<1>(rin, rout, s_l4, s_edge, tid); break;
        case 2: stream_phase<2>(rin, rout, s_l4, s_edge, tid); break;
        default: stream_phase<3>(rin, rout, s_l4, s_edge, tid); break;
    }
    __syncthreads();
    if (lb != 0 && tid < 256) s_l4[tid * 16] += s_edge[tid];  // add b-edges
    __syncthreads();

    // ---- Level 3: 512 parents from clamped L4 values ----
    {
        const float4* p = reinterpret_cast<const float4*>(s_l4) + 2 * tid;
        float4 va = p[0], vb = p[1];
        float c0 = __saturatef(va.x), c1 = __saturatef(va.y);
        float c2 = __saturatef(va.z), c3 = __saturatef(va.w);
        float c4 = __saturatef(vb.x), c5 = __saturatef(vb.y);
        float c6 = __saturatef(vb.z), c7 = __saturatef(vb.w);
        const float* swp = g_sw + L4_START + 8 * tid;
        float v = c0 * __ldg(swp + 0) + c1 * __ldg(swp + 1)
                + c2 * __ldg(swp + 2) + c3 * __ldg(swp + 3)
                + c4 * __ldg(swp + 4) + c5 * __ldg(swp + 5)
                + c6 * __ldg(swp + 6) + c7 * __ldg(swp + 7);
        s_l3[tid] = __saturatef(v);
    }
    __syncthreads();

    // ---- Level 2 ----
    if (tid < 64) {
        const float4* p = reinterpret_cast<const float4*>(s_l3) + 2 * tid;
        float4 va = p[0], vb = p[1];
        const float* swp = g_sw + L3_START + 8 * tid;
        float v = va.x * __ldg(swp + 0) + va.y * __ldg(swp + 1)
                + va.z * __ldg(swp + 2) + va.w * __ldg(swp + 3)
                + vb.x * __ldg(swp + 4) + vb.y * __ldg(swp + 5)
                + vb.z * __ldg(swp + 6) + vb.w * __ldg(swp + 7);
        s_l2[tid] = __saturatef(v);
    }
    __syncthreads();

    // ---- Level 1 ----
    if (tid < 8) {
        const float4* p = reinterpret_cast<const float4*>(s_l2) + 2 * tid;
        float4 va = p[0], vb = p[1];
        const float* swp = g_sw + L2_START + 8 * tid;
        float v = va.x * __ldg(swp + 0) + va.y * __ldg(swp + 1)
                + va.z * __ldg(swp + 2) + va.w * __ldg(swp + 3)
                + vb.x * __ldg(swp + 4) + vb.y * __ldg(swp + 5)
                + vb.z * __ldg(swp + 6) + vb.w * __ldg(swp + 7);
        s_l1[tid] = __saturatef(v);
    }
    __syncthreads();

    // ---- Root ----
    if (tid == 0) {
        const float4* p = reinterpret_cast<const float4*>(s_l1);
        float4 va = p[0], vb = p[1];
        const float* swp = g_sw + L1_START;
        float v = va.x * __ldg(swp + 0) + va.y * __ldg(swp + 1)
                + va.z * __ldg(swp + 2) + va.w * __ldg(swp + 3)
                + vb.x * __ldg(swp + 4) + vb.y * __ldg(swp + 5)
                + vb.z * __ldg(swp + 6) + vb.w * __ldg(swp + 7);
        rout[0] = __saturatef(v);
    }

    // ---- Write internal levels (coalesced) ----
    #pragma unroll
    for (int it = 0; it < 8; ++it) {
        int i = it * 512 + tid;
        rout[L4_START + i] = __saturatef(s_l4[i]);
    }
    rout[L3_START + tid] = s_l3[tid];
    if (tid < 64) rout[L2_START + tid] = s_l2[tid];
    if (tid < 8)  rout[L1_START + tid] = s_l1[tid];
}

extern "C" void kernel_launch(void* const* d_in, const int* in_sizes, int n_in,
                              void* d_out, int out_size) {
    const float* probs = (const float*)d_in[0];   // [2048, 37449] fp32
    const float* w     = (const float*)d_in[1];   // [37449] fp32
    float* out         = (float*)d_out;

    const int batch = in_sizes[0] / NN;           // 2048

    setup_kernel<<<(NN + 255) / 256, 256>>>(w);
    tree_kernel<<<batch, 512>>>(probs, out);
}

// round 4
// speedup vs baseline: 1.1147x; 1.0970x over previous
#include <cuda_runtime.h>

#define NN        37449   // total nodes
#define L5_START  4681    // leaf level start
#define L5_COUNT  32768
#define L4_START  585
#define L4_COUNT  4096
#define L3_START  73
#define L2_START  9
#define L1_START  1

// sigmoid(w) for all nodes (internal-level dots + head/tail scalars)
__device__ float g_sw[NN];
// 4 shifted copies of the leaf section: copy s stores leaf l at index
// ((4-s)&3)+l. For LB=s, vector k's leaves start at copy index
// ((4-s)&3)+s+4k (= 4+4k for s>0, 4k for s=0) -> 16B aligned.
__device__ __align__(16) float g_swl[4][L5_COUNT + 4];

__global__ void setup_kernel(const float* __restrict__ w) {
    int i = blockIdx.x * blockDim.x + threadIdx.x;
    if (i >= NN) return;
    float sv = 1.0f / (1.0f + __expf(-w[i]));
    g_sw[i] = sv;
    int l = i - L5_START;
    if (l >= 0) {
        #pragma unroll
        for (int s = 0; s < 4; ++s)
            g_swl[s][((4 - s) & 3) + l] = sv;
    }
}

// Per-vector parent-contribution math. Vector k covers leaves [LB+4k, LB+4k+4).
// s = full 4-dot, a = low-parent part, b = high-parent part.
template<int LB>
__device__ __forceinline__ void vec_contrib(const float4& x, const float4& sv,
                                            int k, float& s, float& a, float& b)
{
    float q0 = x.x * sv.x, q1 = x.y * sv.y, q2 = x.z * sv.z, q3 = x.w * sv.w;
    s = (q0 + q1) + (q2 + q3);
    if (LB == 0) {
        a = s; b = 0.f;
    } else {
        float ao, bo;
        if (LB == 1) { ao = (q0 + q1) + q2; bo = q3; }
        if (LB == 2) { ao = q0 + q1;        bo = q2 + q3; }
        if (LB == 3) { ao = q0;             bo = (q1 + q2) + q3; }
        bool odd = (k & 1);
        a = odd ? ao : s;
        b = odd ? bo : 0.f;
    }
}

// Gather 3 shuffles -> parent slot m = b[2m-1] + s[2m] + a[2m+1], store to smem.
template<int LB>
__device__ __forceinline__ void emit_parents(float s, float a, float b,
                                             float* __restrict__ s_l4,
                                             float* __restrict__ s_edge,
                                             int it, int warp, int lane)
{
    float ss = __shfl_sync(0xffffffffu, s, (2 * lane)      & 31);
    float aa = __shfl_sync(0xffffffffu, a, (2 * lane + 1)  & 31);
    float bb = __shfl_sync(0xffffffffu, b, (2 * lane + 31) & 31);
    if (lane < 16) {
        float val = ss + aa;
        if (lane > 0) val += bb;            // lane-0 parents get b in fixup pass
        s_l4[it * 256 + warp * 16 + lane] = val;
    }
    if (LB != 0 && lane == 31)
        s_edge[it * 16 + warp + 1] = b;     // edge into next slot's first parent
}

template<int LB>
__device__ __forceinline__ void stream_phase(
    const float* __restrict__ rin, float* __restrict__ rout,
    float* __restrict__ s_l4, float* __restrict__ s_edge, int tid)
{
    const float4* __restrict__ in4  = reinterpret_cast<const float4*>(rin  + L5_START + LB);
    float4*       __restrict__ out4 = reinterpret_cast<float4*>(rout + L5_START + LB);
    // 16B-aligned base: copy index ((4-LB)&3)+LB  (0 for LB==0, 4 otherwise)
    const float4* __restrict__ sw4  =
        reinterpret_cast<const float4*>(&g_swl[LB][((4 - LB) & 3) + LB]);
    const int lane = tid & 31;
    const int warp = tid >> 5;

    // ---- Main loop: 15 clean iterations (default-cached ld/st: let L2 keep
    // input across graph replays and absorb rewritten output lines) ----
    #pragma unroll 5
    for (int it = 0; it < 15; ++it) {
        const int k = it * 512 + tid;
        float4 x  = __ldg(in4 + k);
        float4 sv = __ldg(sw4 + k);
        out4[k] = x;
        float s, a, b;
        vec_contrib<LB>(x, sv, k, s, a, b);
        emit_parents<LB>(s, a, b, s_l4, s_edge, it, warp, lane);
    }

    // ---- Peeled last iteration (it == 15): vector 8191 may be clipped ----
    {
        const int k = 15 * 512 + tid;
        float4 x, sv;
        if (LB == 0 || k != 8191) {
            x  = __ldg(in4 + k);
            sv = __ldg(sw4 + k);
            out4[k] = x;
        } else {
            float xt[4] = {0.f, 0.f, 0.f, 0.f};
            float st[4] = {0.f, 0.f, 0.f, 0.f};
            const float* rp = rin  + L5_START + LB + 32764;
            float*       wp = rout + L5_START + LB + 32764;
            const float* sp = &g_swl[LB][((4 - LB) & 3) + LB + 32764];
            #pragma unroll
            for (int j = 0; j < 4 - LB; ++j) {
                xt[j] = rp[j]; st[j] = sp[j]; wp[j] = xt[j];
            }
            x  = make_float4(xt[0], xt[1], xt[2], xt[3]);
            sv = make_float4(st[0], st[1], st[2], st[3]);
        }
        float s, a, b;
        vec_contrib<LB>(x, sv, k, s, a, b);
        emit_parents<LB>(s, a, b, s_l4, s_edge, 15, warp, lane);
    }

    if (LB != 0 && tid == 0) {
        // Head leaves 0..LB-1 belong to parent 0.
        float h = 0.f;
        #pragma unroll
        for (int j = 0; j < LB; ++j) {
            float xv = rin[L5_START + j];
            rout[L5_START + j] = xv;
            h += xv * g_sw[L5_START + j];
        }
        s_edge[0] = h;
    }
}

__global__ __launch_bounds__(512)
void tree_kernel(const float* __restrict__ in, float* __restrict__ out)
{
    __shared__ __align__(16) float s_l4[L4_COUNT];   // raw (pre-clamp) parent sums
    __shared__ float s_edge[260];
    __shared__ __align__(16) float s_l3[512];
    __shared__ __align__(16) float s_l2[64];
    __shared__ __align__(16) float s_l1[8];

    const int tid = threadIdx.x;
    const int r   = blockIdx.x;
    const float* __restrict__ rin  = in  + (size_t)r * NN;
    float*       __restrict__ rout = out + (size_t)r * NN;
    const int lb = (4 - ((r + 1) & 3)) & 3;   // leaf-base alignment for this row

    switch (lb) {
        case 0: stream_phase<0>(rin, rout, s_l4, s_edge, tid); break;
        case 1: stream_phase<1>(rin, rout, s_l4, s_edge, tid); break;
        case 2: stream_phase<2>(rin, rout, s_l4, s_edge, tid); break;
        default: stream_phase<3>(rin, rout, s_l4, s_edge, tid); break;
    }
    __syncthreads();
    if (lb != 0 && tid < 256) s_l4[tid * 16] += s_edge[tid];  // add b-edges
    __syncthreads();

    // ---- Level 3: 512 parents from clamped L4 values ----
    {
        const float4* p = reinterpret_cast<const float4*>(s_l4) + 2 * tid;
        float4 va = p[0], vb = p[1];
        float c0 = __saturatef(va.x), c1 = __saturatef(va.y);
        float c2 = __saturatef(va.z), c3 = __saturatef(va.w);
        float c4 = __saturatef(vb.x), c5 = __saturatef(vb.y);
        float c6 = __saturatef(vb.z), c7 = __saturatef(vb.w);
        const float* swp = g_sw + L4_START + 8 * tid;
        float v = c0 * __ldg(swp + 0) + c1 * __ldg(swp + 1)
                + c2 * __ldg(swp + 2) + c3 * __ldg(swp + 3)
                + c4 * __ldg(swp + 4) + c5 * __ldg(swp + 5)
                + c6 * __ldg(swp + 6) + c7 * __ldg(swp + 7);
        s_l3[tid] = __saturatef(v);
    }
    __syncthreads();

    // ---- Level 2 ----
    if (tid < 64) {
        const float4* p = reinterpret_cast<const float4*>(s_l3) + 2 * tid;
        float4 va = p[0], vb = p[1];
        const float* swp = g_sw + L3_START + 8 * tid;
        float v = va.x * __ldg(swp + 0) + va.y * __ldg(swp + 1)
                + va.z * __ldg(swp + 2) + va.w * __ldg(swp + 3)
                + vb.x * __ldg(swp + 4) + vb.y * __ldg(swp + 5)
                + vb.z * __ldg(swp + 6) + vb.w * __ldg(swp + 7);
        s_l2[tid] = __saturatef(v);
    }
    __syncthreads();

    // ---- Level 1 ----
    if (tid < 8) {
        const float4* p = reinterpret_cast<const float4*>(s_l2) + 2 * tid;
        float4 va = p[0], vb = p[1];
        const float* swp = g_sw + L2_START + 8 * tid;
        float v = va.x * __ldg(swp + 0) + va.y * __ldg(swp + 1)
                + va.z * __ldg(swp + 2) + va.w * __ldg(swp + 3)
                + vb.x * __ldg(swp + 4) + vb.y * __ldg(swp + 5)
                + vb.z * __ldg(swp + 6) + vb.w * __ldg(swp + 7);
        s_l1[tid] = __saturatef(v);
    }
    __syncthreads();

    // ---- Root ----
    if (tid == 0) {
        const float4* p = reinterpret_cast<const float4*>(s_l1);
        float4 va = p[0], vb = p[1];
        const float* swp = g_sw + L1_START;
        float v = va.x * __ldg(swp + 0) + va.y * __ldg(swp + 1)
                + va.z * __ldg(swp + 2) + va.w * __ldg(swp + 3)
                + vb.x * __ldg(swp + 4) + vb.y * __ldg(swp + 5)
                + vb.z * __ldg(swp + 6) + vb.w * __ldg(swp + 7);
        rout[0] = __saturatef(v);
    }

    // ---- Write internal levels (coalesced) ----
    #pragma unroll
    for (int it = 0; it < 8; ++it) {
        int i = it * 512 + tid;
        rout[L4_START + i] = __saturatef(s_l4[i]);
    }
    rout[L3_START + tid] = s_l3[tid];
    if (tid < 64) rout[L2_START + tid] = s_l2[tid];
    if (tid < 8)  rout[L1_START + tid] = s_l1[tid];
}

extern "C" void kernel_launch(void* const* d_in, const int* in_sizes, int n_in,
                              void* d_out, int out_size) {
    const float* probs = (const float*)d_in[0];   // [2048, 37449] fp32
    const float* w     = (const float*)d_in[1];   // [37449] fp32
    float* out         = (float*)d_out;

    const int batch = in_sizes[0] / NN;           // 2048

    setup_kernel<<<(NN + 255) / 256, 256>>>(w);
    tree_kernel<<<batch, 512>>>(probs, out);
}